// round 2
// baseline (speedup 1.0000x reference)
#include <cuda_runtime.h>
#include <cstdint>

#define T_TOKENS 16384
#define DIMX     2048
#define NE       8
#define KSEL     2048

// libdevice exp (exact same bits as XLA-GPU's exp lowering), immune to fast-math.
extern "C" __device__ float __nv_expf(float);

// Scratch: final logits [e][t]
__device__ float g_logits[NE * T_TOKENS];

// ---------------------------------------------------------------------------
// Kernel 1: logits. One thread = one token, full 2048-dim in-order FMA chain
// per expert (bitwise = reference's single-accumulator ascending-k FMA).
// Experts packed in pairs via fma.rn.f32x2 (lane-wise identical to fma.rn.f32).
// W interleaved [d][e] in smem (broadcast reads), x tile staged pitch-68.
// ---------------------------------------------------------------------------
#define TILE_T     128
#define K1_THREADS 128
#define CHUNK_D    64
#define XPITCH     68   // 17 float4-banks -> conflict-free LDS.128

__global__ void __launch_bounds__(K1_THREADS) k1_gemv(const float* __restrict__ x,
                                                      const float* __restrict__ W)
{
    extern __shared__ float sm1[];
    float* sw = sm1;                        // [DIMX][NE] interleaved = 64 KB
    float* sx = sm1 + DIMX * NE;            // [TILE_T][XPITCH]

    const int tile = blockIdx.x;
    const int tid  = threadIdx.x;

    // Load full W (8 x 2048) interleaved: sw[d*8 + e] = W[e][d].
    for (int i = tid; i < NE * DIMX; i += K1_THREADS) {
        int e = i >> 11;          // i / 2048
        int d = i & 2047;
        sw[d * NE + e] = W[i];
    }
    __syncthreads();

    // 4 packed accumulators = experts (0,1)(2,3)(4,5)(6,7); start at +0.0f.
    unsigned long long acc0 = 0ull, acc1 = 0ull, acc2 = 0ull, acc3 = 0ull;

    const size_t rowBase = (size_t)tile * TILE_T;

    for (int ch = 0; ch < DIMX / CHUNK_D; ++ch) {
        // Stage 128 tokens x 64 dims, coalesced LDG.128.
        for (int i = tid; i < TILE_T * (CHUNK_D / 4); i += K1_THREADS) {
            int row = i >> 4;
            int c4  = i & 15;
            const float4* src = reinterpret_cast<const float4*>(
                x + (rowBase + (size_t)row) * DIMX + ch * CHUNK_D);
            *reinterpret_cast<float4*>(&sx[row * XPITCH + c4 * 4]) = src[c4];
        }
        __syncthreads();

#pragma unroll
        for (int c4 = 0; c4 < CHUNK_D / 4; ++c4) {
            float4 xv = *reinterpret_cast<const float4*>(&sx[tid * XPITCH + c4 * 4]);
            const float* wd = &sw[(ch * CHUNK_D + c4 * 4) * NE];
#pragma unroll
            for (int q = 0; q < 4; ++q) {
                float xs = (q == 0) ? xv.x : (q == 1) ? xv.y : (q == 2) ? xv.z : xv.w;
                unsigned long long xx;
                asm("mov.b64 %0, {%1, %1};" : "=l"(xx) : "f"(xs));
                // LDS.128 of 4 packed expert-pairs (broadcast across warp).
                ulonglong2 wA = *reinterpret_cast<const ulonglong2*>(wd + q * NE);     // e0..e3
                ulonglong2 wB = *reinterpret_cast<const ulonglong2*>(wd + q * NE + 4); // e4..e7
                asm("fma.rn.f32x2 %0, %1, %2, %0;" : "+l"(acc0) : "l"(xx), "l"(wA.x));
                asm("fma.rn.f32x2 %0, %1, %2, %0;" : "+l"(acc1) : "l"(xx), "l"(wA.y));
                asm("fma.rn.f32x2 %0, %1, %2, %0;" : "+l"(acc2) : "l"(xx), "l"(wB.x));
                asm("fma.rn.f32x2 %0, %1, %2, %0;" : "+l"(acc3) : "l"(xx), "l"(wB.y));
            }
        }
        __syncthreads();
    }

    const int token = tile * TILE_T + tid;
    float r[NE];
    asm("mov.b64 {%0, %1}, %2;" : "=f"(r[0]), "=f"(r[1]) : "l"(acc0));
    asm("mov.b64 {%0, %1}, %2;" : "=f"(r[2]), "=f"(r[3]) : "l"(acc1));
    asm("mov.b64 {%0, %1}, %2;" : "=f"(r[4]), "=f"(r[5]) : "l"(acc2));
    asm("mov.b64 {%0, %1}, %2;" : "=f"(r[6]), "=f"(r[7]) : "l"(acc3));
#pragma unroll
    for (int e = 0; e < NE; ++e)
        g_logits[e * T_TOKENS + token] = r[e];
}

// ---------------------------------------------------------------------------
// Kernel 2: per-expert exact top-2048 (sorted desc, ties -> lower index).
// key = (~bits(sigmoid) << 32) | token; ascending key == jax.lax.top_k order.
// Exact radix select over 6 digit levels, collect 2048, bitonic sort.
// ---------------------------------------------------------------------------
#define K2_THREADS 1024

__global__ void __launch_bounds__(K2_THREADS) k2_topk(float* __restrict__ out, int writeIdx)
{
    extern __shared__ unsigned char sm2[];
    unsigned int*        keys  = reinterpret_cast<unsigned int*>(sm2);            // 16384 u32
    unsigned int*        hist  = reinterpret_cast<unsigned int*>(sm2 + 65536);    // 2048 u32
    unsigned int*        hscan = hist + 2048;                                     // 2048 u32
    unsigned long long*  sel   = reinterpret_cast<unsigned long long*>(sm2 + 65536 + 16384); // 2048 u64

    __shared__ unsigned long long s_pref;
    __shared__ unsigned long long s_mask;
    __shared__ int          s_want;
    __shared__ int          s_bin;
    __shared__ unsigned int s_before;
    __shared__ int          s_n;

    const int e   = blockIdx.x;
    const int tid = threadIdx.x;
    const unsigned lane = tid & 31;

    const float* lg = &g_logits[e * T_TOKENS];

    for (int i = tid; i < T_TOKENS; i += K2_THREADS) {
        float l  = lg[i];
        // XLA logistic expansion (exp form), bit-matched: 1 / (1 + exp(-x))
        float em = __nv_expf(-l);
        float s  = __fdiv_rn(1.0f, __fadd_rn(1.0f, em));
        keys[i] = ~__float_as_uint(s);        // s>0 -> bits monotone; ascending key == desc score
    }
    if (tid == 0) { s_pref = 0ull; s_mask = 0ull; s_want = KSEL; s_n = 0; }
    __syncthreads();

    const int shifts[6] = {53, 42, 31, 20, 9, 0};
    const int nbits [6] = {11, 11, 11, 11, 11, 9};

    for (int lvl = 0; lvl < 6; ++lvl) {
        const int shift = shifts[lvl];
        const int nb    = 1 << nbits[lvl];
        const int wantLoc              = s_want;
        const unsigned long long mask  = s_mask;
        const unsigned long long pref  = s_pref;

        for (int i = tid; i < nb; i += K2_THREADS) hist[i] = 0u;
        __syncthreads();

        for (int i = tid; i < T_TOKENS; i += K2_THREADS) {
            unsigned long long K = ((unsigned long long)keys[i] << 32) | (unsigned)i;
            bool m = ((K & mask) == pref);
            unsigned active = __ballot_sync(0xffffffffu, m);
            if (m) {
                int bin = (int)((K >> shift) & (unsigned)(nb - 1));
                unsigned same = __match_any_sync(active, bin);
                if ((int)lane == (__ffs(same) - 1))
                    atomicAdd(&hist[bin], (unsigned)__popc(same));
            }
        }
        __syncthreads();

        unsigned int* src = hist;
        unsigned int* dst = hscan;
        for (int off = 1; off < nb; off <<= 1) {
            for (int i = tid; i < nb; i += K2_THREADS)
                dst[i] = src[i] + (i >= off ? src[i - off] : 0u);
            __syncthreads();
            unsigned int* t = src; src = dst; dst = t;
        }

        for (int i = tid; i < nb; i += K2_THREADS) {
            unsigned c = src[i];
            unsigned p = (i > 0) ? src[i - 1] : 0u;
            if ((int)c >= wantLoc && (int)p < wantLoc) { s_bin = i; s_before = p; }
        }
        __syncthreads();
        if (tid == 0) {
            s_want = wantLoc - (int)s_before;
            s_pref = pref | ((unsigned long long)(unsigned)s_bin << shift);
            s_mask = mask | ((unsigned long long)(unsigned)(nb - 1) << shift);
        }
        __syncthreads();
    }

    const unsigned long long Kstar = s_pref;   // exact 2048th-smallest key

    for (int i = tid; i < T_TOKENS; i += K2_THREADS) {
        unsigned long long K = ((unsigned long long)keys[i] << 32) | (unsigned)i;
        bool take = (K <= Kstar);
        unsigned bal = __ballot_sync(0xffffffffu, take);
        int base = 0;
        if (lane == 0 && bal) base = atomicAdd(&s_n, __popc(bal));
        base = __shfl_sync(0xffffffffu, base, 0);
        if (take) {
            int pos = base + __popc(bal & ((1u << lane) - 1u));
            sel[pos] = K;
        }
    }
    __syncthreads();

    for (int k = 2; k <= KSEL; k <<= 1) {
        for (int j = k >> 1; j > 0; j >>= 1) {
            int i = ((tid & ~(j - 1)) << 1) | (tid & (j - 1));
            int l = i | j;
            unsigned long long a = sel[i];
            unsigned long long b = sel[l];
            bool asc = ((i & k) == 0);
            if ((a > b) == asc) { sel[i] = b; sel[l] = a; }
            __syncthreads();
        }
    }

    for (int r = tid; r < KSEL; r += K2_THREADS) {
        unsigned long long K = sel[r];
        float score = __uint_as_float(~(unsigned)(K >> 32));
        out[e * KSEL + r] = score;
        if (writeIdx)
            out[NE * KSEL + e * KSEL + r] = (float)(unsigned)(K & 0xffffffffu);
    }
}

// ---------------------------------------------------------------------------
extern "C" void kernel_launch(void* const* d_in, const int* in_sizes, int n_in,
                              void* d_out, int out_size)
{
    const float* x = (const float*)d_in[0];   // [16384, 2048] f32
    const float* W = (const float*)d_in[1];   // [8, 2048] f32
    float* out = (float*)d_out;

    const int SMEM1 = (DIMX * NE + TILE_T * XPITCH) * (int)sizeof(float); // 100352
    const int SMEM2 = 65536 + 8192 + 8192 + 16384;                        // 98304

    cudaFuncSetAttribute(k1_gemv, cudaFuncAttributeMaxDynamicSharedMemorySize, SMEM1);
    cudaFuncSetAttribute(k2_topk, cudaFuncAttributeMaxDynamicSharedMemorySize, SMEM2);

    const int writeIdx = (out_size >= 2 * NE * KSEL) ? 1 : 0;

    k1_gemv<<<T_TOKENS / TILE_T, K1_THREADS, SMEM1>>>(x, W);
    k2_topk<<<NE, K2_THREADS, SMEM2>>>(out, writeIdx);
}

// round 3
// speedup vs baseline: 1.9477x; 1.9477x over previous
#include <cuda_runtime.h>
#include <cstdint>

#define T_TOKENS 16384
#define DIMX     2048
#define NE       8
#define KSEL     2048

// libdevice exp — exact bits, immune to fast-math flags.
extern "C" __device__ float __nv_expf(float);

// Scratch: per-expert sort keys, key = ~bits(sigmoid(logit)). [e][t]
__device__ unsigned int g_keys[NE * T_TOKENS];

// ---------------------------------------------------------------------------
// Kernel 1: logits + keys. 4 threads per token, each owns one expert-pair's
// full 2048-dim in-order fma.rn.f32x2 chain (bitwise identical to the R2
// single-thread version: same pairs, same ascending-d order, same instruction).
// 512 thr/block => 4 warps/SMSP to hide LDS latency.
// ---------------------------------------------------------------------------
#define TILE_T     128
#define K1_THREADS 512
#define XPITCH     68            // conflict-free LDS.128 for x
#define WPITCH     (4096 + 4)    // pair array: 2048 dims x 2 + 16B pad (bank skew)

__global__ void __launch_bounds__(K1_THREADS) k1_gemv(const float* __restrict__ x,
                                                      const float* __restrict__ W)
{
    extern __shared__ float sm1[];
    float* swp = sm1;                       // [4][WPITCH]  (~65.6 KB)
    float* sx  = sm1 + 4 * WPITCH;          // [TILE_T][XPITCH] (~34.8 KB)

    const int tid = threadIdx.x;

    // W interleave: swp[p][d*2 + half] = W[2p+half][d]
    for (int i = tid; i < NE * DIMX; i += K1_THREADS) {
        int e = i >> 11;
        int d = i & 2047;
        swp[(e >> 1) * WPITCH + d * 2 + (e & 1)] = W[i];
    }
    __syncthreads();

    const int tloc = tid >> 2;          // token within tile
    const int pair = tid & 3;           // expert pair (0,1)(2,3)(4,5)(6,7)
    const float* wbase = swp + pair * WPITCH;

    unsigned long long acc = 0ull;      // (+0.0f, +0.0f)
    const size_t rowBase = (size_t)blockIdx.x * TILE_T;

    for (int ch = 0; ch < DIMX / 64; ++ch) {
        // Stage 128 tokens x 64 dims, coalesced LDG.128.
        for (int i = tid; i < TILE_T * 16; i += K1_THREADS) {
            int row = i >> 4;
            int c4  = i & 15;
            const float4* src = reinterpret_cast<const float4*>(
                x + (rowBase + (size_t)row) * DIMX + ch * 64);
            *reinterpret_cast<float4*>(&sx[row * XPITCH + c4 * 4]) = src[c4];
        }
        __syncthreads();

#pragma unroll
        for (int c4 = 0; c4 < 16; ++c4) {
            float4 xv = *reinterpret_cast<const float4*>(&sx[tloc * XPITCH + c4 * 4]);
            const float* wd = wbase + (ch * 64 + c4 * 4) * 2;
            ulonglong2 wA = *reinterpret_cast<const ulonglong2*>(wd);       // dims d0, d0+1
            ulonglong2 wB = *reinterpret_cast<const ulonglong2*>(wd + 4);   // dims d0+2, d0+3
            unsigned long long x0, x1, x2, x3;
            asm("mov.b64 %0, {%1, %1};" : "=l"(x0) : "f"(xv.x));
            asm("mov.b64 %0, {%1, %1};" : "=l"(x1) : "f"(xv.y));
            asm("mov.b64 %0, {%1, %1};" : "=l"(x2) : "f"(xv.z));
            asm("mov.b64 %0, {%1, %1};" : "=l"(x3) : "f"(xv.w));
            asm("fma.rn.f32x2 %0, %1, %2, %0;" : "+l"(acc) : "l"(x0), "l"(wA.x));
            asm("fma.rn.f32x2 %0, %1, %2, %0;" : "+l"(acc) : "l"(x1), "l"(wA.y));
            asm("fma.rn.f32x2 %0, %1, %2, %0;" : "+l"(acc) : "l"(x2), "l"(wB.x));
            asm("fma.rn.f32x2 %0, %1, %2, %0;" : "+l"(acc) : "l"(x3), "l"(wB.y));
        }
        __syncthreads();
    }

    float r0, r1;
    asm("mov.b64 {%0, %1}, %2;" : "=f"(r0), "=f"(r1) : "l"(acc));

    // sigmoid (exp form, bit-matched) -> monotone descending key
    float em0 = __nv_expf(-r0);
    float em1 = __nv_expf(-r1);
    float s0  = __fdiv_rn(1.0f, __fadd_rn(1.0f, em0));
    float s1  = __fdiv_rn(1.0f, __fadd_rn(1.0f, em1));

    const int token = (int)rowBase + tloc;
    g_keys[(2 * pair)     * T_TOKENS + token] = ~__float_as_uint(s0);
    g_keys[(2 * pair + 1) * T_TOKENS + token] = ~__float_as_uint(s1);
}

// ---------------------------------------------------------------------------
// Kernel 2: per-expert exact top-2048 (desc, ties -> lower index).
// 64-bit key K = (score_key << 32) | token; ascending K == jax.lax.top_k order.
// Radix select with warp-hierarchical scans + early exit, then bitonic sort.
// ---------------------------------------------------------------------------
#define K2_THREADS 1024

__global__ void __launch_bounds__(K2_THREADS) k2_topk(float* __restrict__ out, int writeIdx)
{
    extern __shared__ unsigned char sm2[];
    unsigned int*        keys  = reinterpret_cast<unsigned int*>(sm2);            // 16384 u32
    unsigned int*        hist  = reinterpret_cast<unsigned int*>(sm2 + 65536);    // 2048 u32
    unsigned int*        hscan = hist + 2048;                                     // 2048 u32
    unsigned long long*  sel   = reinterpret_cast<unsigned long long*>(sm2 + 65536 + 16384); // 2048 u64

    __shared__ unsigned int s_wsum[32];
    __shared__ unsigned long long s_pref;
    __shared__ unsigned long long s_mask;
    __shared__ int          s_want;
    __shared__ int          s_bin;
    __shared__ unsigned int s_before;
    __shared__ int          s_exact;
    __shared__ int          s_n;

    const int e    = blockIdx.x;
    const int tid  = threadIdx.x;
    const unsigned lane = tid & 31;
    const int wid  = tid >> 5;

    const unsigned int* gk = &g_keys[e * T_TOKENS];
    for (int i = tid; i < T_TOKENS; i += K2_THREADS)
        keys[i] = gk[i];

    if (tid == 0) { s_pref = 0ull; s_mask = 0ull; s_want = KSEL; s_exact = 0; s_n = 0; }
    __syncthreads();

    const int shifts[6] = {53, 42, 31, 20, 9, 0};
    const int nbits [6] = {11, 11, 11, 11, 11, 9};

    unsigned long long Kstar = 0ull;

    for (int lvl = 0; lvl < 6; ++lvl) {
        const int shift = shifts[lvl];
        const int nb    = 1 << nbits[lvl];
        const int wantLoc              = s_want;
        const unsigned long long mask  = s_mask;
        const unsigned long long pref  = s_pref;

        for (int i = tid; i < nb; i += K2_THREADS) hist[i] = 0u;
        __syncthreads();

        // Histogram of current digit among prefix-matching keys (warp-aggregated).
        for (int i = tid; i < T_TOKENS; i += K2_THREADS) {
            unsigned long long K = ((unsigned long long)keys[i] << 32) | (unsigned)i;
            bool m = ((K & mask) == pref);
            unsigned active = __ballot_sync(0xffffffffu, m);
            if (m) {
                int bin = (int)((K >> shift) & (unsigned)(nb - 1));
                unsigned same = __match_any_sync(active, bin);
                if ((int)lane == (__ffs(same) - 1))
                    atomicAdd(&hist[bin], (unsigned)__popc(same));
            }
        }
        __syncthreads();

        // Hierarchical inclusive scan: 2 bins/thread -> warp shfl scan -> warp sums.
        {
            int b0 = 2 * tid, b1 = 2 * tid + 1;
            unsigned v0 = (b0 < nb) ? hist[b0] : 0u;
            unsigned v1 = (b1 < nb) ? hist[b1] : 0u;
            unsigned sthr = v0 + v1;
            unsigned si = sthr;
#pragma unroll
            for (int o = 1; o < 32; o <<= 1) {
                unsigned n = __shfl_up_sync(0xffffffffu, si, o);
                if (lane >= (unsigned)o) si += n;
            }
            if (lane == 31) s_wsum[wid] = si;
            __syncthreads();
            if (wid == 0) {
                unsigned w = s_wsum[lane];
                unsigned wi = w;
#pragma unroll
                for (int o = 1; o < 32; o <<= 1) {
                    unsigned n = __shfl_up_sync(0xffffffffu, wi, o);
                    if (lane >= (unsigned)o) wi += n;
                }
                s_wsum[lane] = wi - w;   // exclusive warp prefix
            }
            __syncthreads();
            unsigned pfx = s_wsum[wid] + (si - sthr);  // exclusive thread prefix
            if (b0 < nb) hscan[b0] = pfx + v0;
            if (b1 < nb) hscan[b1] = pfx + v0 + v1;
        }
        __syncthreads();

        // Boundary bin: first bin whose cumulative count reaches wantLoc.
        for (int i = tid; i < nb; i += K2_THREADS) {
            unsigned c = hscan[i];
            unsigned p = (i > 0) ? hscan[i - 1] : 0u;
            if ((int)c >= wantLoc && (int)p < wantLoc) {
                s_bin = i; s_before = p;
                if ((int)c == wantLoc) s_exact = 1;  // whole bin selected
            }
        }
        __syncthreads();
        if (tid == 0) {
            s_want = wantLoc - (int)s_before;
            s_pref = pref | ((unsigned long long)(unsigned)s_bin << shift);
            s_mask = mask | ((unsigned long long)(unsigned)(nb - 1) << shift);
        }
        __syncthreads();
        if (s_exact) { Kstar = s_pref | ~s_mask; break; }
    }

    // Collect exactly 2048 keys <= Kstar (keys unique: index in low bits).
    for (int i = tid; i < T_TOKENS; i += K2_THREADS) {
        unsigned long long K = ((unsigned long long)keys[i] << 32) | (unsigned)i;
        bool take = (K <= Kstar);
        unsigned bal = __ballot_sync(0xffffffffu, take);
        int base = 0;
        if (lane == 0 && bal) base = atomicAdd(&s_n, __popc(bal));
        base = __shfl_sync(0xffffffffu, base, 0);
        if (take) {
            int pos = base + __popc(bal & ((1u << lane) - 1u));
            sel[pos] = K;
        }
    }
    __syncthreads();

    // Bitonic sort ascending: 2048 u64, 1 compare-exchange per thread per step.
    for (int k = 2; k <= KSEL; k <<= 1) {
        for (int j = k >> 1; j > 0; j >>= 1) {
            int i = ((tid & ~(j - 1)) << 1) | (tid & (j - 1));
            int l = i | j;
            unsigned long long a = sel[i];
            unsigned long long b = sel[l];
            bool asc = ((i & k) == 0);
            if ((a > b) == asc) { sel[i] = b; sel[l] = a; }
            __syncthreads();
        }
    }

    for (int r = tid; r < KSEL; r += K2_THREADS) {
        unsigned long long K = sel[r];
        float score = __uint_as_float(~(unsigned)(K >> 32));
        out[e * KSEL + r] = score;
        if (writeIdx)
            out[NE * KSEL + e * KSEL + r] = (float)(unsigned)(K & 0xffffffffu);
    }
}

// ---------------------------------------------------------------------------
extern "C" void kernel_launch(void* const* d_in, const int* in_sizes, int n_in,
                              void* d_out, int out_size)
{
    const float* x = (const float*)d_in[0];   // [16384, 2048] f32
    const float* W = (const float*)d_in[1];   // [8, 2048] f32
    float* out = (float*)d_out;

    const int SMEM1 = (4 * WPITCH + TILE_T * XPITCH) * (int)sizeof(float); // 100416
    const int SMEM2 = 65536 + 8192 + 8192 + 16384;                         // 98304

    cudaFuncSetAttribute(k1_gemv, cudaFuncAttributeMaxDynamicSharedMemorySize, SMEM1);
    cudaFuncSetAttribute(k2_topk, cudaFuncAttributeMaxDynamicSharedMemorySize, SMEM2);

    const int writeIdx = (out_size >= 2 * NE * KSEL) ? 1 : 0;

    k1_gemv<<<T_TOKENS / TILE_T, K1_THREADS, SMEM1>>>(x, W);
    k2_topk<<<NE, K2_THREADS, SMEM2>>>(out, writeIdx);
}

// round 4
// speedup vs baseline: 3.0542x; 1.5681x over previous
#include <cuda_runtime.h>
#include <cstdint>

#define T_TOKENS 16384
#define DIMX     2048
#define NE       8
#define KSEL     2048

// libdevice exp — exact bits, immune to fast-math flags.
extern "C" __device__ float __nv_expf(float);

// Scratch: per-expert sort keys, key = ~bits(sigmoid(logit)). [e][t]
__device__ unsigned int g_keys[NE * T_TOKENS];

// ---------------------------------------------------------------------------
// Kernel 1: logits + keys. 8 threads per token; thread (t,e) runs the full
// 2048-dim in-order scalar fma.rn chain (bitwise == the passing R3 kernel:
// f32x2 lanes are exactly scalar fma.rn in the same d order). No inline asm,
// so ptxas can software-pipeline. 2 blocks/SM -> 8 warps/SMSP; register
// prefetch double-buffers the x tile against DRAM latency.
// ---------------------------------------------------------------------------
#define TILE_T     64
#define K1_THREADS 512
#define XPITCH     68    // 64 tokens x 68 floats: conflict-free LDS.128
#define WP         2052  // per-expert row pitch: 8208B, 16e-byte bank skew

__global__ void __launch_bounds__(K1_THREADS) k1_gemv(const float* __restrict__ x,
                                                      const float* __restrict__ W)
{
    extern __shared__ float sm1[];
    float* sw = sm1;                 // [NE][WP]   ~65.7 KB
    float* sx = sm1 + NE * WP;       // [TILE_T][XPITCH] ~17.4 KB

    const int tid = threadIdx.x;

    // Load W rows (coalesced LDG, coalesced STS).
    for (int i = tid; i < NE * DIMX; i += K1_THREADS) {
        int e = i >> 11;
        int d = i & 2047;
        sw[e * WP + d] = W[i];
    }

    const int tloc = tid >> 3;       // token within tile (0..63)
    const int e    = tid & 7;        // expert
    const size_t rowBase = (size_t)blockIdx.x * TILE_T;
    const float* wrow = sw + e * WP;

    // Stage indices: 1024 float4 per tile-chunk, 2 per thread.
    const int r0 = tid >> 4,          c0 = tid & 15;
    const int r1 = (tid + 512) >> 4,  c1 = (tid + 512) & 15;

    float4 p0, p1;
    {
        const float* base = x + rowBase * DIMX;
        p0 = *reinterpret_cast<const float4*>(base + (size_t)r0 * DIMX + c0 * 4);
        p1 = *reinterpret_cast<const float4*>(base + (size_t)r1 * DIMX + c1 * 4);
    }

    float acc = 0.0f;

    for (int ch = 0; ch < DIMX / 64; ++ch) {
        __syncthreads();   // prev compute done (and sw ready on ch==0)
        *reinterpret_cast<float4*>(&sx[r0 * XPITCH + c0 * 4]) = p0;
        *reinterpret_cast<float4*>(&sx[r1 * XPITCH + c1 * 4]) = p1;
        __syncthreads();   // sx visible

        if (ch + 1 < DIMX / 64) {   // prefetch next chunk (overlaps compute)
            const float* base = x + rowBase * DIMX + (ch + 1) * 64;
            p0 = *reinterpret_cast<const float4*>(base + (size_t)r0 * DIMX + c0 * 4);
            p1 = *reinterpret_cast<const float4*>(base + (size_t)r1 * DIMX + c1 * 4);
        }

        const float* xd = sx + tloc * XPITCH;
        const float* wd = wrow + ch * 64;
#pragma unroll
        for (int c4 = 0; c4 < 16; ++c4) {
            float4 xv = *reinterpret_cast<const float4*>(xd + c4 * 4);
            float4 wv = *reinterpret_cast<const float4*>(wd + c4 * 4);
            acc = __fmaf_rn(xv.x, wv.x, acc);
            acc = __fmaf_rn(xv.y, wv.y, acc);
            acc = __fmaf_rn(xv.z, wv.z, acc);
            acc = __fmaf_rn(xv.w, wv.w, acc);
        }
    }

    // sigmoid (exp form, bit-matched) -> monotone descending key
    float em = __nv_expf(-acc);
    float s  = __fdiv_rn(1.0f, __fadd_rn(1.0f, em));
    g_keys[e * T_TOKENS + (int)rowBase + tloc] = ~__float_as_uint(s);
}

// ---------------------------------------------------------------------------
// Kernel 2: per-expert exact top-2048 (desc, ties -> lower index).
// 64-bit key K = (score_key << 32) | token; ascending K == jax.lax.top_k order.
// Radix select (warp scans + early exit) then HYBRID bitonic sort:
// j>=64 stages in smem (15 barriered stages), j<=32 stages in registers/shfl.
// ---------------------------------------------------------------------------
#define K2_THREADS 1024

__global__ void __launch_bounds__(K2_THREADS) k2_topk(float* __restrict__ out, int writeIdx)
{
    extern __shared__ unsigned char sm2[];
    unsigned int*        keys  = reinterpret_cast<unsigned int*>(sm2);            // 16384 u32
    unsigned int*        hist  = reinterpret_cast<unsigned int*>(sm2 + 65536);    // 2048 u32
    unsigned int*        hscan = hist + 2048;                                     // 2048 u32
    unsigned long long*  sel   = reinterpret_cast<unsigned long long*>(sm2 + 65536 + 16384); // 2048 u64

    __shared__ unsigned int s_wsum[32];
    __shared__ unsigned long long s_pref;
    __shared__ unsigned long long s_mask;
    __shared__ int          s_want;
    __shared__ int          s_bin;
    __shared__ unsigned int s_before;
    __shared__ int          s_exact;
    __shared__ int          s_n;

    const int e    = blockIdx.x;
    const int tid  = threadIdx.x;
    const unsigned lane = tid & 31;
    const int wid  = tid >> 5;

    const unsigned int* gk = &g_keys[e * T_TOKENS];
    for (int i = tid; i < T_TOKENS; i += K2_THREADS)
        keys[i] = gk[i];

    if (tid == 0) { s_pref = 0ull; s_mask = 0ull; s_want = KSEL; s_exact = 0; s_n = 0; }
    __syncthreads();

    const int shifts[6] = {53, 42, 31, 20, 9, 0};
    const int nbits [6] = {11, 11, 11, 11, 11, 9};

    unsigned long long Kstar = 0ull;

    for (int lvl = 0; lvl < 6; ++lvl) {
        const int shift = shifts[lvl];
        const int nb    = 1 << nbits[lvl];
        const int wantLoc              = s_want;
        const unsigned long long mask  = s_mask;
        const unsigned long long pref  = s_pref;

        for (int i = tid; i < nb; i += K2_THREADS) hist[i] = 0u;
        __syncthreads();

        for (int i = tid; i < T_TOKENS; i += K2_THREADS) {
            unsigned long long K = ((unsigned long long)keys[i] << 32) | (unsigned)i;
            bool m = ((K & mask) == pref);
            unsigned active = __ballot_sync(0xffffffffu, m);
            if (m) {
                int bin = (int)((K >> shift) & (unsigned)(nb - 1));
                unsigned same = __match_any_sync(active, bin);
                if ((int)lane == (__ffs(same) - 1))
                    atomicAdd(&hist[bin], (unsigned)__popc(same));
            }
        }
        __syncthreads();

        // Hierarchical inclusive scan: 2 bins/thread -> warp scan -> warp sums.
        {
            int b0 = 2 * tid, b1 = 2 * tid + 1;
            unsigned v0 = (b0 < nb) ? hist[b0] : 0u;
            unsigned v1 = (b1 < nb) ? hist[b1] : 0u;
            unsigned sthr = v0 + v1;
            unsigned si = sthr;
#pragma unroll
            for (int o = 1; o < 32; o <<= 1) {
                unsigned n = __shfl_up_sync(0xffffffffu, si, o);
                if (lane >= (unsigned)o) si += n;
            }
            if (lane == 31) s_wsum[wid] = si;
            __syncthreads();
            if (wid == 0) {
                unsigned w = s_wsum[lane];
                unsigned wi = w;
#pragma unroll
                for (int o = 1; o < 32; o <<= 1) {
                    unsigned n = __shfl_up_sync(0xffffffffu, wi, o);
                    if (lane >= (unsigned)o) wi += n;
                }
                s_wsum[lane] = wi - w;
            }
            __syncthreads();
            unsigned pfx = s_wsum[wid] + (si - sthr);
            if (b0 < nb) hscan[b0] = pfx + v0;
            if (b1 < nb) hscan[b1] = pfx + v0 + v1;
        }
        __syncthreads();

        for (int i = tid; i < nb; i += K2_THREADS) {
            unsigned c = hscan[i];
            unsigned p = (i > 0) ? hscan[i - 1] : 0u;
            if ((int)c >= wantLoc && (int)p < wantLoc) {
                s_bin = i; s_before = p;
                if ((int)c == wantLoc) s_exact = 1;
            }
        }
        __syncthreads();
        if (tid == 0) {
            s_want = wantLoc - (int)s_before;
            s_pref = pref | ((unsigned long long)(unsigned)s_bin << shift);
            s_mask = mask | ((unsigned long long)(unsigned)(nb - 1) << shift);
        }
        __syncthreads();
        if (s_exact) { Kstar = s_pref | ~s_mask; break; }
    }
    if (Kstar == 0ull) Kstar = s_pref | ~s_mask;  // (level-6 exit always exact; belt+braces)

    // Collect exactly 2048 keys <= Kstar.
    for (int i = tid; i < T_TOKENS; i += K2_THREADS) {
        unsigned long long K = ((unsigned long long)keys[i] << 32) | (unsigned)i;
        bool take = (K <= Kstar);
        unsigned bal = __ballot_sync(0xffffffffu, take);
        int base = 0;
        if (lane == 0 && bal) base = atomicAdd(&s_n, __popc(bal));
        base = __shfl_sync(0xffffffffu, base, 0);
        if (take) {
            int pos = base + __popc(bal & ((1u << lane) - 1u));
            sel[pos] = K;
        }
    }
    __syncthreads();

    // ---- Hybrid bitonic sort ascending over sel[2048] ----
    // Thread owns positions g0 = warp*64 + lane, g1 = g0 + 32.
    const int g0 = (wid << 6) | (int)lane;
    const int g1 = g0 + 32;
    unsigned long long a = sel[g0];
    unsigned long long b = sel[g1];

    for (int k = 2; k <= KSEL; k <<= 1) {
        int j = k >> 1;
        if (j >= 64) {
            sel[g0] = a; sel[g1] = b;
            __syncthreads();
            for (; j >= 64; j >>= 1) {
                int i = ((tid & ~(j - 1)) << 1) | (tid & (j - 1));
                int l = i | j;
                unsigned long long u = sel[i];
                unsigned long long v = sel[l];
                bool asc = ((i & k) == 0);
                if ((u > v) == asc) { sel[i] = v; sel[l] = u; }
                __syncthreads();
            }
            a = sel[g0]; b = sel[g1];   // j == 32 now
        }
        for (; j >= 1; j >>= 1) {
            if (j == 32) {
                bool asc = ((g0 & k) == 0);
                if ((a > b) == asc) { unsigned long long t = a; a = b; b = t; }
            } else {
                unsigned long long pa = __shfl_xor_sync(0xffffffffu, a, j);
                unsigned long long pb = __shfl_xor_sync(0xffffffffu, b, j);
                bool lower = ((lane & (unsigned)j) == 0u);
                bool ascA  = ((g0 & k) == 0);
                bool ascB  = ((g1 & k) == 0);
                unsigned long long amin = (a < pa) ? a : pa;
                unsigned long long amax = (a < pa) ? pa : a;
                unsigned long long bmin = (b < pb) ? b : pb;
                unsigned long long bmax = (b < pb) ? pb : b;
                a = (lower == ascA) ? amin : amax;
                b = (lower == ascB) ? bmin : bmax;
            }
        }
    }

    // Emit directly from registers.
    {
        float scA = __uint_as_float(~(unsigned)(a >> 32));
        float scB = __uint_as_float(~(unsigned)(b >> 32));
        out[e * KSEL + g0] = scA;
        out[e * KSEL + g1] = scB;
        if (writeIdx) {
            out[NE * KSEL + e * KSEL + g0] = (float)(unsigned)(a & 0xffffffffu);
            out[NE * KSEL + e * KSEL + g1] = (float)(unsigned)(b & 0xffffffffu);
        }
    }
}

// ---------------------------------------------------------------------------
extern "C" void kernel_launch(void* const* d_in, const int* in_sizes, int n_in,
                              void* d_out, int out_size)
{
    const float* x = (const float*)d_in[0];   // [16384, 2048] f32
    const float* W = (const float*)d_in[1];   // [8, 2048] f32
    float* out = (float*)d_out;

    const int SMEM1 = (NE * WP + TILE_T * XPITCH) * (int)sizeof(float); // 83072
    const int SMEM2 = 65536 + 8192 + 8192 + 16384;                      // 98304

    cudaFuncSetAttribute(k1_gemv, cudaFuncAttributeMaxDynamicSharedMemorySize, SMEM1);
    cudaFuncSetAttribute(k2_topk, cudaFuncAttributeMaxDynamicSharedMemorySize, SMEM2);

    const int writeIdx = (out_size >= 2 * NE * KSEL) ? 1 : 0;

    k1_gemv<<<T_TOKENS / TILE_T, K1_THREADS, SMEM1>>>(x, W);
    k2_topk<<<NE, K2_THREADS, SMEM2>>>(out, writeIdx);
}